// round 17
// baseline (speedup 1.0000x reference)
#include <cuda_runtime.h>
#include <cuda_bf16.h>
#include <math.h>
#include <stdint.h>

// ---------------- scratch (device globals; no allocation allowed) ----------
__device__ float    g_l[8*256*64*64];      // encoder feature map l (fp32, raw)
__device__ float    g_D1p[64*256];         // Dict^T B-frags for GEMM1 (tf32)
__device__ float    g_D2p[64*256];         // Dict/L B-frags for GEMM2 (tf32)
__device__ uint32_t g_xpk[8*32*4096];      // x packed bf16 pairs
__device__ uint32_t g_lpk[8*128*4096];     // relu(l) packed bf16 pairs
__device__ uint32_t g_tpk[8*64*4096];      // relu(t) packed bf16 pairs
__device__ uint4    g_w3af[9*4*16*32];     // conv1 w frag-packed [tap][ch][ocg][lane]
__device__ uint4    g_w3b1f[9*16*8*32];    // res1 w1 frag-packed
__device__ uint4    g_w3b2f[9*16*8*32];    // res2 w1 frag-packed
__device__ uint32_t g_w1a[256*64];         // res1 w2 packed   [oc][k/2]
__device__ uint32_t g_w1b[256*64];         // res2 w2 packed
__device__ float    g_avg[8*256];
__device__ float    g_mx[8*256];
__device__ float    g_catt[8*256];
__device__ float    g_s2[8*2*64*64];
__device__ float    g_satt[8*64*64];

static __device__ __forceinline__ float softt(float v, float la) {
    float a = fabsf(v) - la;
    a = a > 0.f ? a : 0.f;
    return copysignf(a, v);
}
static __device__ __forceinline__ float sigmoidf_(float v) {
    return 1.f / (1.f + expf(-v));
}
static __device__ __forceinline__ uint32_t f2tf32(float f) {
    uint32_t r;
    asm("cvt.rna.tf32.f32 %0, %1;" : "=r"(r) : "f"(f));
    return r;
}
static __device__ __forceinline__ uint32_t packbf2(float a, float b) {
    __nv_bfloat162 h = __floats2bfloat162_rn(a, b);
    return *(uint32_t*)&h;
}
static __device__ __forceinline__ void mma_tf32(float* c, const uint32_t* a,
                                                uint32_t b0, uint32_t b1) {
    asm volatile(
        "mma.sync.aligned.m16n8k8.row.col.f32.tf32.tf32.f32 "
        "{%0,%1,%2,%3}, {%4,%5,%6,%7}, {%8,%9}, {%0,%1,%2,%3};\n"
        : "+f"(c[0]), "+f"(c[1]), "+f"(c[2]), "+f"(c[3])
        : "r"(a[0]), "r"(a[1]), "r"(a[2]), "r"(a[3]), "r"(b0), "r"(b1));
}
static __device__ __forceinline__ void mma_bf16(float* c, const uint32_t* a,
                                                uint32_t b0, uint32_t b1) {
    asm volatile(
        "mma.sync.aligned.m16n8k16.row.col.f32.bf16.bf16.f32 "
        "{%0,%1,%2,%3}, {%4,%5,%6,%7}, {%8,%9}, {%0,%1,%2,%3};\n"
        : "+f"(c[0]), "+f"(c[1]), "+f"(c[2]), "+f"(c[3])
        : "r"(a[0]), "r"(a[1]), "r"(a[2]), "r"(a[3]), "r"(b0), "r"(b1));
}
static __device__ __forceinline__ uint32_t smem_u32(const void* p) {
    return (uint32_t)__cvta_generic_to_shared(p);
}
static __device__ __forceinline__ void cp4(uint32_t dst, const void* src, bool pred) {
    int sz = pred ? 4 : 0;
    asm volatile("cp.async.ca.shared.global [%0], [%1], 4, %2;\n"
                 :: "r"(dst), "l"(src), "r"(sz));
}
static __device__ __forceinline__ void cp16(uint32_t dst, const void* src) {
    asm volatile("cp.async.cg.shared.global [%0], [%1], 16;\n"
                 :: "r"(dst), "l"(src));
}
static __device__ __forceinline__ void cp_commit() {
    asm volatile("cp.async.commit_group;\n");
}
template<int N> static __device__ __forceinline__ void cp_wait() {
    asm volatile("cp.async.wait_group %0;\n" :: "n"(N));
}

// ---------------- Dict fragment packing for factorized LISTA ---------------
__global__ void pack_D1_kernel(const float* __restrict__ Dict) {
    int i = blockIdx.x*256 + threadIdx.x;      // 8192 pairs
    int kc = i >> 8, rem = i & 255;
    int n = rem >> 2, t = rem & 3;
    float2* dst = (float2*)g_D1p;
    float2 v;
    v.x = __uint_as_float(f2tf32(Dict[n*256 + kc*8 + t]));
    v.y = __uint_as_float(f2tf32(Dict[n*256 + kc*8 + t + 4]));
    dst[i] = v;
}
__global__ void pack_D2_kernel(const float* __restrict__ Dict,
                               const float* __restrict__ Lp) {
    int i = blockIdx.x*256 + threadIdx.x;      // 8192 pairs
    float invL = 1.f / *Lp;
    int kc = i >> 10, rem = i & 1023;
    int n = rem >> 2, t = rem & 3;
    float2* dst = (float2*)g_D2p;
    float2 v;
    v.x = __uint_as_float(f2tf32(Dict[(kc*8 + t    )*256 + n] * invL));
    v.y = __uint_as_float(f2tf32(Dict[(kc*8 + t + 4)*256 + n] * invL));
    dst[i] = v;
}

// ---------------- pack kernels (fp32 -> bf16 channel-pair u32) -------------
__global__ void pack_pairs_kernel(const float* __restrict__ src,
                                  uint32_t* __restrict__ dst, int totalU32) {
    int i = blockIdx.x*256 + threadIdx.x;
    if (i >= totalU32) return;
    int q = i >> 12, px = i & 4095;
    float v0 = src[((size_t)(2*q))*4096 + px];
    float v1 = src[((size_t)(2*q+1))*4096 + px];
    dst[i] = packbf2(v0, v1);
}
// 3x3 weights OIHW -> mma-A-fragment uint4: [tap][ch][ocg16][lane]
// lane (g,t): u = { (oc g, pr t), (oc g+8, pr t), (oc g, pr t+4), (oc g+8, pr t+4) }
__global__ void pack_w3f_kernel(const float* __restrict__ w,
                                uint4* __restrict__ dst, int Cin, int Cout) {
    int NCH = Cin >> 4, OCG = Cout >> 4;
    int total = 9*NCH*OCG*32;
    int i = blockIdx.x*256 + threadIdx.x;
    if (i >= total) return;
    int lane = i & 31;
    int r = i >> 5;
    int ocg = r % OCG; r /= OCG;
    int ch = r % NCH;
    int tap = r / NCH;
    int g = lane >> 2, t = lane & 3;
    int oc0 = ocg*16 + g, oc1 = oc0 + 8;
    int pr0 = ch*8 + t, pr1 = pr0 + 4;
    uint4 u;
    u.x = packbf2(w[((size_t)oc0*Cin + 2*pr0)*9 + tap], w[((size_t)oc0*Cin + 2*pr0+1)*9 + tap]);
    u.y = packbf2(w[((size_t)oc1*Cin + 2*pr0)*9 + tap], w[((size_t)oc1*Cin + 2*pr0+1)*9 + tap]);
    u.z = packbf2(w[((size_t)oc0*Cin + 2*pr1)*9 + tap], w[((size_t)oc0*Cin + 2*pr1+1)*9 + tap]);
    u.w = packbf2(w[((size_t)oc1*Cin + 2*pr1)*9 + tap], w[((size_t)oc1*Cin + 2*pr1+1)*9 + tap]);
    dst[i] = u;
}
__global__ void pack_w1_kernel(const float* __restrict__ w,
                               uint32_t* __restrict__ dst) {
    int i = blockIdx.x*256 + threadIdx.x;   // 256*64 total
    int oc = i >> 6, pr = i & 63;
    dst[i] = packbf2(w[oc*128 + 2*pr], w[oc*128 + 2*pr + 1]);
}

// ---------------- 3x3 conv, pad 1, bf16 m16n8k16, 32oc x 256px tiles -------
// 16x16 spatial tile (N=256 px), 32 oc (M). 8 warps all along N (32 px each).
// ic chunks of 16 (8 bf16 pairs). Weights pre-packed as uint4 A-fragments.
#define C3_XS   2624                  // 8*328 u32 per x buffer
#define C3_WS4  576                   // 9*2*32 uint4 per w buffer
#define CONV3_SMEM (2*C3_XS*4 + 2*C3_WS4*16)

template<int CIN, bool OUT_F32, bool BIAS>
__global__ __launch_bounds__(256, 3) void conv3x3_bf16(
    const uint32_t* __restrict__ apk,   // [b][CIN/2][4096]
    const uint4*    __restrict__ wf,    // [tap][ch][OCGT][32]
    const float* __restrict__ bias,
    float* __restrict__ outf,           // [b][Cout][4096] raw
    uint32_t* __restrict__ outpk,       // [b][Cout/2][4096] relu packed
    int Cout)
{
    extern __shared__ __align__(16) uint32_t sm[];
    uint32_t* xsb = sm;                         // [2][8 pr][18x18 pitch 328]
    uint4*    wsb = (uint4*)(sm + 2*C3_XS);     // [2][tap9][ocg2][32]

    int b    = blockIdx.x >> 4;
    int tile = blockIdx.x & 15;
    int oy0  = (tile >> 2) << 4;
    int ox0  = (tile & 3) << 4;
    int ocBase = blockIdx.y << 5;               // 32 oc per CTA
    int OCGT   = Cout >> 4;
    int ocgB   = blockIdx.y << 1;

    int tid  = threadIdx.x;
    int lane = tid & 31, wn = tid >> 5;         // all 8 warps along N
    int g = lane >> 2, t = lane & 3;

    const int C2  = CIN >> 1;
    const int NCH = CIN >> 4;

    float acc[2][4][4];
#pragma unroll
    for (int am = 0; am < 2; am++)
#pragma unroll
        for (int ng = 0; ng < 4; ng++)
#pragma unroll
            for (int j = 0; j < 4; j++) acc[am][ng][j] = 0.f;

    auto stage = [&](int ch, int bi) {
        int pr0 = ch << 3;
        uint32_t* xs = xsb + bi*C3_XS;
        uint4*    ws = wsb + bi*C3_WS4;
        for (int i = tid; i < 8*324; i += 256) {
            int pp = i / 324, rem = i - pp*324;
            int r = rem / 18, c = rem - r*18;
            int gy = oy0 - 1 + r, gx = ox0 - 1 + c;
            bool ok = ((unsigned)gy < 64u) && ((unsigned)gx < 64u);
            const uint32_t* src = ok
                ? apk + ((size_t)(b*C2 + pr0 + pp))*4096 + gy*64 + gx
                : apk;
            cp4(smem_u32(xs + pp*328 + rem), src, ok);
        }
        for (int i = tid; i < C3_WS4; i += 256) {
            int ln = i & 31, q = i >> 5;
            int ocg = q & 1, tap = q >> 1;
            cp16(smem_u32(ws + i),
                 wf + ((size_t)(tap*NCH + ch)*OCGT + ocgB + ocg)*32 + ln);
        }
        cp_commit();
    };

    stage(0, 0);
    for (int ch = 0; ch < NCH; ch++) {
        if (ch + 1 < NCH) { stage(ch + 1, (ch + 1) & 1); cp_wait<1>(); }
        else              { cp_wait<0>(); }
        __syncthreads();

        const uint32_t* xs = xsb + (ch & 1)*C3_XS;
        const uint4*    ws = wsb + (ch & 1)*C3_WS4;
#pragma unroll
        for (int kh = 0; kh < 3; kh++) {
#pragma unroll
            for (int kw = 0; kw < 3; kw++) {
                int tap = kh*3 + kw;
                uint4 av0 = ws[(tap*2 + 0)*32 + lane];
                uint4 av1 = ws[(tap*2 + 1)*32 + lane];
                uint32_t a0[4] = {av0.x, av0.y, av0.z, av0.w};
                uint32_t a1[4] = {av1.x, av1.y, av1.z, av1.w};
#pragma unroll
                for (int ng = 0; ng < 4; ng++) {
                    int r  = wn*2 + (ng >> 1);
                    int c0 = (ng & 1) << 3;
                    const uint32_t* xp = xs + (r+kh)*18 + c0 + kw + g;
                    uint32_t b0 = xp[ t   *328];
                    uint32_t b1 = xp[(t+4)*328];
                    mma_bf16(acc[0][ng], a0, b0, b1);
                    mma_bf16(acc[1][ng], a1, b0, b1);
                }
            }
        }
        __syncthreads();
    }

    int C2o = Cout >> 1;
#pragma unroll
    for (int am = 0; am < 2; am++) {
        int oc0 = ocBase + am*16 + g;
        float bv0 = BIAS ? bias[oc0]     : 0.f;
        float bv1 = BIAS ? bias[oc0 + 8] : 0.f;
#pragma unroll
        for (int ng = 0; ng < 4; ng++) {
            int r = wn*2 + (ng >> 1);
            int c = ((ng & 1) << 3) + 2*t;
            float r00 = acc[am][ng][0]+bv0, r01 = acc[am][ng][1]+bv0;
            float r10 = acc[am][ng][2]+bv1, r11 = acc[am][ng][3]+bv1;
            if (OUT_F32) {
                size_t o0 = ((size_t)(b*Cout + oc0)*64 + oy0 + r)*64 + ox0 + c;
                size_t o1 = o0 + (size_t)8*64*64;
                *(float2*)(outf + o0) = make_float2(r00, r01);
                *(float2*)(outf + o1) = make_float2(r10, r11);
            }
            float p0 = fmaxf(r00, 0.f), p1 = fmaxf(r01, 0.f);
            float p2 = fmaxf(r10, 0.f), p3 = fmaxf(r11, 0.f);
            float q0 = __shfl_down_sync(0xffffffffu, p0, 4);
            float q1 = __shfl_down_sync(0xffffffffu, p1, 4);
            float q2 = __shfl_down_sync(0xffffffffu, p2, 4);
            float q3 = __shfl_down_sync(0xffffffffu, p3, 4);
            if ((g & 1) == 0) {
                int ocp = oc0 >> 1;
                size_t base = ((size_t)(b*C2o + ocp))*4096 + (oy0 + r)*64 + ox0 + c;
                *(uint2*)(outpk + base)                  = make_uint2(packbf2(p0, q0), packbf2(p1, q1));
                *(uint2*)(outpk + base + (size_t)4*4096) = make_uint2(packbf2(p2, q2), packbf2(p3, q3));
            }
        }
    }
}

// ---------------- 1x1 conv + residual add, bf16 m16n8k16 -------------------
template<bool PACK>
__global__ __launch_bounds__(256) void conv1x1_bf16(
    const uint32_t* __restrict__ tpk,   // [b][64][4096]
    const uint32_t* __restrict__ wpk,   // [oc256][64]
    float* __restrict__ l,              // in/out fp32
    uint32_t* __restrict__ lpk_out)     // [b][128][4096] relu packed
{
    __shared__ __align__(16) uint32_t ts[2][8*264];
    __shared__ __align__(16) uint32_t ws[2][64*12];

    int b   = blockIdx.x >> 4;
    int px0 = (blockIdx.x & 15) << 8;
    int ocBase = blockIdx.y << 6;
    int tid  = threadIdx.x;
    int lane = tid & 31, warp = tid >> 5;
    int wm = warp >> 2, wn = warp & 3;
    int g = lane >> 2, tt = lane & 3;

    float acc[2][8][4];
#pragma unroll
    for (int am = 0; am < 2; am++)
#pragma unroll
        for (int ng = 0; ng < 8; ng++)
#pragma unroll
            for (int j = 0; j < 4; j++) acc[am][ng][j] = 0.f;

    auto stage = [&](int ch, int bi) {
        int pr0 = ch << 3;
        for (int i = tid; i < 512; i += 256) {
            int pp = i >> 6, p4 = (i & 63) << 2;
            cp16(smem_u32(&ts[bi][pp*264 + p4]),
                 tpk + ((size_t)(b*64 + pr0 + pp))*4096 + px0 + p4);
        }
        if (tid < 128) {
            int oc = tid >> 1, half = tid & 1;
            cp16(smem_u32(&ws[bi][oc*12 + half*4]),
                 wpk + (size_t)(ocBase + oc)*64 + pr0 + half*4);
        }
        cp_commit();
    };

    stage(0, 0);
    for (int ch = 0; ch < 8; ch++) {
        if (ch + 1 < 8) { stage(ch + 1, (ch + 1) & 1); cp_wait<1>(); }
        else            { cp_wait<0>(); }
        __syncthreads();

        const uint32_t* tsb = ts[ch & 1];
        const uint32_t* wsb = ws[ch & 1];
        uint32_t a[2][4];
#pragma unroll
        for (int am = 0; am < 2; am++) {
            const uint32_t* wp = wsb + (wm*32 + am*16)*12;
            a[am][0] = wp[(g  )*12 + tt];
            a[am][1] = wp[(g+8)*12 + tt];
            a[am][2] = wp[(g  )*12 + tt+4];
            a[am][3] = wp[(g+8)*12 + tt+4];
        }
#pragma unroll
        for (int ng = 0; ng < 8; ng++) {
            int n0 = wn*64 + ng*8;
            uint32_t b0 = tsb[(tt  )*264 + n0 + g];
            uint32_t b1 = tsb[(tt+4)*264 + n0 + g];
            mma_bf16(acc[0][ng], a[0], b0, b1);
            mma_bf16(acc[1][ng], a[1], b0, b1);
        }
        __syncthreads();
    }

#pragma unroll
    for (int am = 0; am < 2; am++) {
        int oc0 = ocBase + wm*32 + am*16 + g;
#pragma unroll
        for (int ng = 0; ng < 8; ng++) {
            int p = px0 + wn*64 + ng*8 + 2*tt;
            size_t o0 = ((size_t)(b*256 + oc0))*4096 + p;
            size_t o1 = o0 + (size_t)8*4096;
            float2 v0 = *(float2*)(l + o0);
            float2 v1 = *(float2*)(l + o1);
            v0.x += acc[am][ng][0]; v0.y += acc[am][ng][1];
            v1.x += acc[am][ng][2]; v1.y += acc[am][ng][3];
            *(float2*)(l + o0) = v0;
            *(float2*)(l + o1) = v1;
            if (PACK) {
                float p0 = fmaxf(v0.x, 0.f), p1 = fmaxf(v0.y, 0.f);
                float p2 = fmaxf(v1.x, 0.f), p3 = fmaxf(v1.y, 0.f);
                float q0 = __shfl_down_sync(0xffffffffu, p0, 4);
                float q1 = __shfl_down_sync(0xffffffffu, p1, 4);
                float q2 = __shfl_down_sync(0xffffffffu, p2, 4);
                float q3 = __shfl_down_sync(0xffffffffu, p3, 4);
                if ((g & 1) == 0) {
                    int ocp = oc0 >> 1;
                    size_t base = ((size_t)(b*128 + ocp))*4096 + p;
                    *(uint2*)(lpk_out + base) =
                        make_uint2(packbf2(p0, q0), packbf2(p1, q1));
                    *(uint2*)(lpk_out + base + (size_t)4*4096) =
                        make_uint2(packbf2(p2, q2), packbf2(p3, q3));
                }
            }
        }
    }
}

// ---------------- channel attention: pooled reductions ---------------------
__global__ void pool_kernel() {
    int bc = blockIdx.x;
    const float* p = g_l + (size_t)bc*4096;
    int tid = threadIdx.x;
    float s = 0.f, m = -3.402823466e38f;
    for (int i = tid; i < 4096; i += 256) {
        float v = p[i];
        s += v; m = fmaxf(m, v);
    }
    __shared__ float ss[256], smx[256];
    ss[tid] = s; smx[tid] = m;
    __syncthreads();
    for (int st = 128; st > 0; st >>= 1) {
        if (tid < st) { ss[tid] += ss[tid+st]; smx[tid] = fmaxf(smx[tid], smx[tid+st]); }
        __syncthreads();
    }
    if (tid == 0) { g_avg[bc] = ss[0] * (1.f/4096.f); g_mx[bc] = smx[0]; }
}

// ---------------- channel attention MLP (tiny) -----------------------------
__global__ void camlp_kernel(const float* __restrict__ w1,
                             const float* __restrict__ w2) {
    int b = blockIdx.x;
    int tid = threadIdx.x;
    __shared__ float av[256], mv[256], ha[16], hm[16];
    av[tid] = g_avg[b*256 + tid];
    mv[tid] = g_mx[b*256 + tid];
    __syncthreads();
    if (tid < 16) {
        float sa = 0.f, sm_ = 0.f;
        for (int c = 0; c < 256; c++) {
            float wv = w1[tid*256 + c];
            sa  += av[c]*wv;
            sm_ += mv[c]*wv;
        }
        ha[tid] = fmaxf(sa, 0.f);
        hm[tid] = fmaxf(sm_, 0.f);
    }
    __syncthreads();
    float oa = 0.f, om = 0.f;
#pragma unroll
    for (int j = 0; j < 16; j++) {
        float wv = w2[tid*16 + j];
        oa += ha[j]*wv;
        om += hm[j]*wv;
    }
    g_catt[b*256 + tid] = sigmoidf_(oa + om);
}

// ---------------- spatial stats of channel-scaled l ------------------------
__global__ void spatial_stats_kernel() {
    int b   = blockIdx.x >> 4;
    int px  = ((blockIdx.x & 15) << 8) + threadIdx.x;
    __shared__ float ca[256];
    ca[threadIdx.x] = g_catt[b*256 + threadIdx.x];
    __syncthreads();
    float s = 0.f, m = -3.402823466e38f;
    for (int ch = 0; ch < 256; ch++) {
        float v = g_l[((size_t)(b*256 + ch))*4096 + px] * ca[ch];
        s += v; m = fmaxf(m, v);
    }
    g_s2[((size_t)(b*2 + 0))*4096 + px] = s * (1.f/256.f);
    g_s2[((size_t)(b*2 + 1))*4096 + px] = m;
}

// ---------------- spatial attention conv (2->1, 3x3, pad1) -----------------
__global__ void saconv_kernel(const float* __restrict__ saw) {
    int b  = blockIdx.x >> 4;
    int px = ((blockIdx.x & 15) << 8) + threadIdx.x;
    int py = px >> 6, pxx = px & 63;
    __shared__ float w[18];
    if (threadIdx.x < 18) w[threadIdx.x] = saw[threadIdx.x];
    __syncthreads();
    float a = 0.f;
#pragma unroll
    for (int ch = 0; ch < 2; ch++)
#pragma unroll
        for (int kh = 0; kh < 3; kh++)
#pragma unroll
            for (int kw = 0; kw < 3; kw++) {
                int gy = py - 1 + kh, gx = pxx - 1 + kw;
                if ((unsigned)gy < 64u && (unsigned)gx < 64u)
                    a += g_s2[((size_t)(b*2 + ch))*4096 + gy*64 + gx] * w[ch*9 + kh*3 + kw];
            }
    g_satt[b*4096 + px] = sigmoidf_(a);
}

// ---------------- LISTA persistent tensor-core kernel (rank-64) ------------
#define ZS_OFF   0
#define YL_OFF   16640
#define LAM_OFF  33280
#define XSH_OFF  49920              // [64][68]: x at init, u in mainloop
#define DSH_OFF  16640
#define LISTA_SMEM ((49920 + 4352) * 4)

__global__ __launch_bounds__(256, 1) void lista_kernel(
    const float* __restrict__ x, const float* __restrict__ Dict,
    const float* __restrict__ Lp, const int* __restrict__ iterp,
    float* __restrict__ zOut, float* __restrict__ xrOut)
{
    extern __shared__ __align__(16) float smem[];
    float* zs  = smem + ZS_OFF;     // [64][260]
    float* yl  = smem + YL_OFF;     // [64][260]
    float* lam = smem + LAM_OFF;    // [64][260]
    float* xsh = smem + XSH_OFF;    // [64][68]  (x, then u)

    int tid = threadIdx.x;
    int gp0 = blockIdx.x * 64;
    int b   = gp0 >> 12;
    int px0 = gp0 & 4095;
    float invL = 1.f / *Lp;
    int iters = *iterp;

    for (int i = tid; i < 4096; i += 256) {
        int c = i >> 6, p = i & 63;
        xsh[p*68 + c] = x[((size_t)(b*64 + c))*4096 + px0 + p];
    }
    for (int i = tid; i < 16384; i += 256) {
        int n = i >> 6, p = i & 63;
        float lv = g_l[((size_t)(b*256 + n))*4096 + px0 + p];
        lam[p*260 + n] = lv * g_catt[b*256 + n] * g_satt[b*4096 + px0 + p] * invL;
    }
    __syncthreads();

    {
        int n0 = tid & 63;
        int pg = tid >> 6;
        float acc[16][4];
#pragma unroll
        for (int p = 0; p < 16; p++)
#pragma unroll
            for (int j = 0; j < 4; j++) acc[p][j] = 0.f;
        for (int c = 0; c < 64; c++) {
            float d0 = Dict[c*256 + n0];
            float d1 = Dict[c*256 + n0 + 64];
            float d2 = Dict[c*256 + n0 + 128];
            float d3 = Dict[c*256 + n0 + 192];
#pragma unroll
            for (int p = 0; p < 16; p++) {
                float xv = xsh[(pg*16 + p)*68 + c];
                acc[p][0] += xv*d0;
                acc[p][1] += xv*d1;
                acc[p][2] += xv*d2;
                acc[p][3] += xv*d3;
            }
        }
#pragma unroll
        for (int p = 0; p < 16; p++)
#pragma unroll
            for (int j = 0; j < 4; j++) {
                int idx = (pg*16 + p)*260 + n0 + 64*j;
                yl[idx] = acc[p][j]*invL;
                float z0 = softt(acc[p][j], lam[idx]);
                zs[idx] = (iters == 0) ? z0 : __uint_as_float(f2tf32(z0));
            }
    }
    __syncthreads();   // xsh (x) dead from here, reused as u

    const int lane = tid & 31;
    const int warp = tid >> 5;
    const int wm   = warp >> 2;
    const int wn   = warp & 3;
    const int g    = lane >> 2;
    const int t    = lane & 3;
    const int mBase = wm*32;
    const int nBase = wn*64;
    float* u = xsh;

    const float2* D1 = (const float2*)g_D1p;
    const float2* D2 = (const float2*)g_D2p;
    int f1[2], f2[8];
#pragma unroll
    for (int nt = 0; nt < 2; nt++) f1[nt] = (wn*16 + nt*8 + g)*4 + t;
#pragma unroll
    for (int nt = 0; nt < 8; nt++) f2[nt] = (nBase + nt*8 + g)*4 + t;

    float2 b1A[2], b1B[2], b2A[8], b2B[8];
#pragma unroll
    for (int nt = 0; nt < 2; nt++) b1A[nt] = __ldg(D1 + f1[nt]);
#pragma unroll
    for (int nt = 0; nt < 8; nt++) b2A[nt] = __ldg(D2 + f2[nt]);

    float acc1[2][2][4];
    float acc2[2][8][4];

    auto kstep1 = [&](int kc, float2 (&bc)[2], float2 (&bn)[2]) {
        int kcn = (kc + 1) & 31;
        const float2* sp = D1 + kcn*256;
        bn[0] = __ldg(sp + f1[0]);
        bn[1] = __ldg(sp + f1[1]);
        int k0 = kc*8;
        uint32_t a[2][4];
#pragma unroll
        for (int am = 0; am < 2; am++) {
            int row = mBase + am*16 + g;
            a[am][0] = __float_as_uint(zs[row*260 + k0 + t]);
            a[am][1] = __float_as_uint(zs[(row+8)*260 + k0 + t]);
            a[am][2] = __float_as_uint(zs[row*260 + k0 + t + 4]);
            a[am][3] = __float_as_uint(zs[(row+8)*260 + k0 + t + 4]);
        }
#pragma unroll
        for (int nt = 0; nt < 2; nt++) {
            uint32_t b0 = __float_as_uint(bc[nt].x);
            uint32_t b1 = __float_as_uint(bc[nt].y);
            mma_tf32(acc1[0][nt], a[0], b0, b1);
            mma_tf32(acc1[1][nt], a[1], b0, b1);
        }
    };
    auto kstep2 = [&](int kc, float2 (&bc)[8], float2 (&bn)[8]) {
        int kcn = (kc + 1) & 7;
        const float2* sp = D2 + kcn*1024;
#pragma unroll
        for (int nt = 0; nt < 8; nt++) bn[nt] = __ldg(sp + f2[nt]);
        int k0 = kc*8;
        uint32_t a[2][4];
#pragma unroll
        for (int am = 0; am < 2; am++) {
            int row = mBase + am*16 + g;
            a[am][0] = __float_as_uint(u[row*68 + k0 + t]);
            a[am][1] = __float_as_uint(u[(row+8)*68 + k0 + t]);
            a[am][2] = __float_as_uint(u[row*68 + k0 + t + 4]);
            a[am][3] = __float_as_uint(u[(row+8)*68 + k0 + t + 4]);
        }
#pragma unroll
        for (int nt = 0; nt < 8; nt++) {
            uint32_t b0 = __float_as_uint(bc[nt].x);
            uint32_t b1 = __float_as_uint(bc[nt].y);
            mma_tf32(acc2[0][nt], a[0], b0, b1);
            mma_tf32(acc2[1][nt], a[1], b0, b1);
        }
    };

    for (int it = 0; it < iters; it++) {
        bool last = (it == iters - 1);

#pragma unroll
        for (int am = 0; am < 2; am++)
#pragma unroll
            for (int nt = 0; nt < 2; nt++)
#pragma unroll
                for (int j = 0; j < 4; j++) acc1[am][nt][j] = 0.f;

        for (int kc = 0; kc < 32; kc += 2) {
            kstep1(kc,     b1A, b1B);
            kstep1(kc + 1, b1B, b1A);
        }
#pragma unroll
        for (int am = 0; am < 2; am++) {
#pragma unroll
            for (int nt = 0; nt < 2; nt++) {
                int row = mBase + am*16 + g;
                int col = wn*16 + nt*8 + 2*t;
                u[row*68 + col]       = __uint_as_float(f2tf32(acc1[am][nt][0]));
                u[row*68 + col + 1]   = __uint_as_float(f2tf32(acc1[am][nt][1]));
                u[(row+8)*68 + col]   = __uint_as_float(f2tf32(acc1[am][nt][2]));
                u[(row+8)*68 + col+1] = __uint_as_float(f2tf32(acc1[am][nt][3]));
            }
        }
        __syncthreads();

#pragma unroll
        for (int am = 0; am < 2; am++)
#pragma unroll
            for (int nt = 0; nt < 8; nt++)
#pragma unroll
                for (int j = 0; j < 4; j++) acc2[am][nt][j] = 0.f;

        for (int kc = 0; kc < 8; kc += 2) {
            kstep2(kc,     b2A, b2B);
            kstep2(kc + 1, b2B, b2A);
        }

#pragma unroll
        for (int am = 0; am < 2; am++) {
#pragma unroll
            for (int nt = 0; nt < 8; nt++) {
                int row = mBase + am*16 + g;
                int col = nBase + nt*8 + 2*t;
                int i0 = row*260 + col;
                int i1 = (row+8)*260 + col;
                float z0 = softt(zs[i0]   - acc2[am][nt][0] + yl[i0],   lam[i0]);
                float z1 = softt(zs[i0+1] - acc2[am][nt][1] + yl[i0+1], lam[i0+1]);
                float z2 = softt(zs[i1]   - acc2[am][nt][2] + yl[i1],   lam[i1]);
                float z3 = softt(zs[i1+1] - acc2[am][nt][3] + yl[i1+1], lam[i1+1]);
                zs[i0]   = last ? z0 : __uint_as_float(f2tf32(z0));
                zs[i0+1] = last ? z1 : __uint_as_float(f2tf32(z1));
                zs[i1]   = last ? z2 : __uint_as_float(f2tf32(z2));
                zs[i1+1] = last ? z3 : __uint_as_float(f2tf32(z3));
            }
        }
        __syncthreads();
    }

    for (int i = tid; i < 16384; i += 256) {
        int n = i >> 6, p = i & 63;
        zOut[((size_t)(b*256 + n))*4096 + px0 + p] = zs[p*260 + n];
    }
    __syncthreads();

    float* dsh = smem + DSH_OFF;
    for (int i = tid; i < 16384; i += 256) {
        int c = i >> 8, a = i & 255;
        dsh[a*68 + c] = Dict[c*256 + a];
    }
    __syncthreads();

    {
        int p = tid & 63, cg = tid >> 6;
        float acc3[16];
#pragma unroll
        for (int j = 0; j < 16; j++) acc3[j] = 0.f;
        for (int a = 0; a < 256; a++) {
            float zv = zs[p*260 + a];
            const float4* dr = (const float4*)&dsh[a*68 + cg*16];
            float4 d0 = dr[0], d1 = dr[1], d2 = dr[2], d3 = dr[3];
            acc3[0]  += zv*d0.x; acc3[1]  += zv*d0.y; acc3[2]  += zv*d0.z; acc3[3]  += zv*d0.w;
            acc3[4]  += zv*d1.x; acc3[5]  += zv*d1.y; acc3[6]  += zv*d1.z; acc3[7]  += zv*d1.w;
            acc3[8]  += zv*d2.x; acc3[9]  += zv*d2.y; acc3[10] += zv*d2.z; acc3[11] += zv*d2.w;
            acc3[12] += zv*d3.x; acc3[13] += zv*d3.y; acc3[14] += zv*d3.z; acc3[15] += zv*d3.w;
        }
#pragma unroll
        for (int j = 0; j < 16; j++)
            xrOut[((size_t)(b*64 + cg*16 + j))*4096 + px0 + p] = acc3[j];
    }
}

// ---------------- launch ----------------------------------------------------
extern "C" void kernel_launch(void* const* d_in, const int* in_sizes, int n_in,
                              void* d_out, int out_size)
{
    const float* x      = (const float*)d_in[0];
    const float* conv_w = (const float*)d_in[1];
    const float* conv_b = (const float*)d_in[2];
    const float* r1w1   = (const float*)d_in[3];
    const float* r1w2   = (const float*)d_in[4];
    const float* r2w1   = (const float*)d_in[5];
    const float* r2w2   = (const float*)d_in[6];
    const float* caw1   = (const float*)d_in[7];
    const float* caw2   = (const float*)d_in[8];
    const float* saw    = (const float*)d_in[9];
    const float* Dict   = (const float*)d_in[10];
    const float* Lp     = (const float*)d_in[11];
    const int*   itp    = (const int*)d_in[12];

    float* out   = (float*)d_out;
    float* zOut  = out;
    float* xrOut = out + (size_t)8*256*4096;
    float* dOut  = xrOut + (size_t)8*64*4096;

    float *lp;
    uint32_t *xpk, *lpk, *tpk, *w1a, *w1b;
    uint4 *w3af, *w3b1f, *w3b2f;
    cudaGetSymbolAddress((void**)&lp,    g_l);
    cudaGetSymbolAddress((void**)&xpk,   g_xpk);
    cudaGetSymbolAddress((void**)&lpk,   g_lpk);
    cudaGetSymbolAddress((void**)&tpk,   g_tpk);
    cudaGetSymbolAddress((void**)&w3af,  g_w3af);
    cudaGetSymbolAddress((void**)&w3b1f, g_w3b1f);
    cudaGetSymbolAddress((void**)&w3b2f, g_w3b2f);
    cudaGetSymbolAddress((void**)&w1a,   g_w1a);
    cudaGetSymbolAddress((void**)&w1b,   g_w1b);

    cudaFuncSetAttribute((const void*)conv3x3_bf16<64, true, true>,
                         cudaFuncAttributeMaxDynamicSharedMemorySize, CONV3_SMEM);
    cudaFuncSetAttribute((const void*)conv3x3_bf16<256, false, false>,
                         cudaFuncAttributeMaxDynamicSharedMemorySize, CONV3_SMEM);
    cudaFuncSetAttribute((const void*)lista_kernel,
                         cudaFuncAttributeMaxDynamicSharedMemorySize, LISTA_SMEM);

    // fragment tables + bf16 packing
    pack_D1_kernel<<<32, 256>>>(Dict);
    pack_D2_kernel<<<32, 256>>>(Dict, Lp);
    pack_pairs_kernel<<<4096, 256>>>(x, xpk, 8*32*4096);
    pack_w3f_kernel<<<72, 256>>>(conv_w, w3af, 64, 256);
    pack_w3f_kernel<<<144, 256>>>(r1w1, w3b1f, 256, 128);
    pack_w3f_kernel<<<144, 256>>>(r2w1, w3b2f, 256, 128);
    pack_w1_kernel<<<64, 256>>>(r1w2, w1a);
    pack_w1_kernel<<<64, 256>>>(r2w2, w1b);

    // encoder
    conv3x3_bf16<64, true, true><<<dim3(128, 8), 256, CONV3_SMEM>>>(
        xpk, w3af, conv_b, lp, lpk, 256);

    conv3x3_bf16<256, false, false><<<dim3(128, 4), 256, CONV3_SMEM>>>(
        lpk, w3b1f, nullptr, nullptr, tpk, 128);
    conv1x1_bf16<true><<<dim3(128, 4), 256>>>(tpk, w1a, lp, lpk);

    conv3x3_bf16<256, false, false><<<dim3(128, 4), 256, CONV3_SMEM>>>(
        lpk, w3b2f, nullptr, nullptr, tpk, 128);
    conv1x1_bf16<false><<<dim3(128, 4), 256>>>(tpk, w1b, lp, nullptr);

    // CBAM attention
    pool_kernel<<<2048, 256>>>();
    camlp_kernel<<<8, 256>>>(caw1, caw2);
    spatial_stats_kernel<<<128, 256>>>();
    saconv_kernel<<<128, 256>>>(saw);

    // LISTA (rank-64 factorized)
    lista_kernel<<<512, 256, LISTA_SMEM>>>(x, Dict, Lp, itp, zOut, xrOut);

    cudaMemcpyAsync(dOut, Dict, (size_t)64*256*sizeof(float), cudaMemcpyDeviceToDevice);
}